// round 16
// baseline (speedup 1.0000x reference)
#include <cuda_runtime.h>
#include <cuda_fp16.h>
#include <math.h>
#include <stdint.h>

#define NEG_SLOPE 0.2f
#define LOG2E 1.4426950408889634f

// Problem constants
#define BS 32
#define NA 512          // n_agents
#define ID 128          // input_dim
#define NH 8            // n_heads
#define HD 64           // hidden_dim

// ---------------------------------------------------------------------------
// Global scratch (prep-kernel outputs)
// ---------------------------------------------------------------------------
__device__ __half g_h16[BS * NA * ID];      // [b][m][pk]        4 MB
__device__ __half g_W16[NH * HD * ID];      // [head][d][pk]     128 KB
__device__ char   g_Edp[BS * NH * 2048];    // per-bh packed Ed granules
__device__ float  g_Es[BS * NH * NA];
__device__ float  g_Es02[BS * NH * NA];

// ---------------------------------------------------------------------------
// helpers
// ---------------------------------------------------------------------------
__device__ __forceinline__ float ex2(float x) {
    float r;
    asm("ex2.approx.f32 %0, %1;" : "=f"(r) : "f"(x));
    return r;
}
__device__ __forceinline__ uint32_t smem_u32(const void* p) {
    uint32_t a;
    asm("{ .reg .u64 t; cvta.to.shared.u64 t, %1; cvt.u32.u64 %0, t; }"
        : "=r"(a) : "l"(p));
    return a;
}
__device__ __forceinline__ void cp_async16(uint32_t dst, const void* src) {
    asm volatile("cp.async.cg.shared.global [%0], [%1], 16;"
                 :: "r"(dst), "l"(src) : "memory");
}
#define CP_COMMIT() asm volatile("cp.async.commit_group;" ::: "memory")
#define CP_WAIT0()  asm volatile("cp.async.wait_group 0;" ::: "memory")
#define CP_WAIT1()  asm volatile("cp.async.wait_group 1;" ::: "memory")

__device__ __forceinline__ void mma_f16(float d[4], uint32_t a0, uint32_t a1,
                                        uint32_t a2, uint32_t a3,
                                        uint32_t b0, uint32_t b1) {
    asm volatile(
        "mma.sync.aligned.m16n8k16.row.col.f32.f16.f16.f32 "
        "{%0,%1,%2,%3}, {%4,%5,%6,%7}, {%8,%9}, {%0,%1,%2,%3};"
        : "+f"(d[0]), "+f"(d[1]), "+f"(d[2]), "+f"(d[3])
        : "r"(a0), "r"(a1), "r"(a2), "r"(a3), "r"(b0), "r"(b1));
}
__device__ __forceinline__ float elu1(float x) {
    return x > 0.f ? x : expm1f(x);
}
__device__ __forceinline__ uint32_t h2u(__half2 v) {
    return *reinterpret_cast<uint32_t*>(&v);
}
__device__ __forceinline__ uint32_t hmul2u(uint32_t x, uint32_t y) {
    __half2 r = __hmul2(*reinterpret_cast<__half2*>(&x),
                        *reinterpret_cast<__half2*>(&y));
    return h2u(r);
}
__device__ __forceinline__ uint32_t hmax2u(uint32_t x, uint32_t y) {
    __half2 r = __hmax2(*reinterpret_cast<__half2*>(&x),
                        *reinterpret_cast<__half2*>(&y));
    return h2u(r);
}

// ---------------------------------------------------------------------------
// Fused prep kernel: grid 256 = (b, head), 512 threads.
//  (a) convert this CTA's 64-row slice of h -> g_h16 (k-permuted fp16)
//  (b) if b == 0: convert this head's W slice -> g_W16
//  (c) e-score tables for (b, head) from fp32 h (es = h . (W a))
// Outputs are independent; consumed by gat_main next launch.
// ---------------------------------------------------------------------------
__global__ void __launch_bounds__(512) prep_all(
    const float* __restrict__ h, const float* __restrict__ W,
    const float* __restrict__ att_a)
{
    __shared__ float a_s[128], wa[128], wb[128], red_s[16];
    const int bh = blockIdx.x, head = bh & 7, b = bh >> 3;
    const int col0 = head * 64;
    const int tid = threadIdx.x, lane = tid & 31, warp = tid >> 5;

    // ---- (a) h conversion: rows [b*512 + head*64, +64), 16 elems/thread ----
    {
        const int row = b * NA + head * 64 + (tid >> 3);   // 64 rows
        const int grp = tid & 7;                           // 8 groups of 16
        const float* src = h + (size_t)row * ID + grp * 16;
        __half* dst = g_h16 + (size_t)row * ID + grp * 16;
        float v[16];
        #pragma unroll
        for (int i = 0; i < 4; i++)
            *(float4*)&v[i * 4] = *(const float4*)&src[i * 4];
        #pragma unroll
        for (int cc = 0; cc < 4; cc++) {
            __half2 lo = __floats2half2_rn(v[2 * cc], v[2 * cc + 1]);
            __half2 hi = __floats2half2_rn(v[2 * cc + 8], v[2 * cc + 9]);
            *(uint2*)(dst + cc * 4) = make_uint2(h2u(lo), h2u(hi));
        }
    }

    // ---- (b) W conversion (b == 0 CTAs only): 8192 elems, 16/thread ----
    if (b == 0) {
        #pragma unroll
        for (int i = 0; i < 16; i++) {
            int idx = tid + i * 512;
            int k = idx >> 6, d = idx & 63;
            float v = W[(size_t)k * 512 + col0 + d];
            int L = k & 15;
            int pk = (k & ~15) + ((L >> 1) & 3) * 4 + ((L >> 3) << 1) + (L & 1);
            g_W16[((head * 64 + d) << 7) + pk] = __float2half_rn(v);
        }
    }

    // ---- (c) e-scores ----
    if (tid < 128) a_s[tid] = att_a[head * 128 + tid];
    __syncthreads();
    if (tid < 128) {
        float sa = 0.f, sb = 0.f;
        const float* wr = W + (size_t)tid * 512 + col0;
        #pragma unroll 8
        for (int d = 0; d < 64; d++) {
            float w = wr[d];
            sa += w * a_s[d];
            sb += w * a_s[64 + d];
        }
        wa[tid] = sa; wb[tid] = sb;
    }
    __syncthreads();

    const int m = tid;
    const float* hr = h + (size_t)(b * NA + m) * ID;
    float es = 0.f, ed = 0.f;
    #pragma unroll 8
    for (int k = 0; k < 128; k += 4) {
        float4 v = *(const float4*)&hr[k];
        es += v.x * wa[k] + v.y * wa[k + 1] + v.z * wa[k + 2] + v.w * wa[k + 3];
        ed += v.x * wb[k] + v.y * wb[k + 1] + v.z * wb[k + 2] + v.w * wb[k + 3];
    }

    // global edmax
    float em = ed;
    #pragma unroll
    for (int o = 16; o; o >>= 1)
        em = fmaxf(em, __shfl_xor_sync(0xFFFFFFFFu, em, o));
    if (lane == 0) red_s[warp] = em;
    __syncthreads();
    em = red_s[0];
    #pragma unroll
    for (int i = 1; i < 16; i++) em = fmaxf(em, red_s[i]);

    const float edl = (ed - em) * LOG2E;
    const __half Edh   = __float2half_rn(ex2(edl));
    const __half Ed02h = __float2half_rn(ex2(NEG_SLOPE * edl));
    {
        const int K = m >> 4, s = (m >> 3) & 1, cc = (m >> 1) & 3, j = m & 1;
        char* g = g_Edp + bh * 2048 + (K * 8 + cc * 2 + s) * 8;
        *(__half*)(g + j * 2)     = Edh;
        *(__half*)(g + 4 + j * 2) = Ed02h;
    }
    const float e0l = (es + em) * LOG2E;
    const float rm = fmaxf(e0l, NEG_SLOPE * e0l);
    g_Es[bh * NA + m]   = ex2(es * LOG2E + em * LOG2E - rm);
    g_Es02[bh * NA + m] = ex2(NEG_SLOPE * e0l - rm);
}

// ---------------------------------------------------------------------------
// Main kernel (unchanged from R15): 256 threads, 2 CTAs/SM, grid 256.
// ---------------------------------------------------------------------------
#define HPTH_S 528
#define OFF_HPT   0                                   // half [64][528] 67584
#define OFF_H16   67584                               // 3 x [256][16] half
#define OFF_EDP   (OFF_H16 + 3 * 8192)                // 92160: 2048 + 64 pad
#define OFF_ES    (OFF_EDP + 2048 + 64)               // 94272
#define OFF_ES02  (OFF_ES + 2048)                     // 96320
#define SMEM_M_BYTES (OFF_ES02 + 2048)                // 98368

__global__ void __launch_bounds__(256, 2) gat_main(float* __restrict__ out) {
    extern __shared__ char smraw[];
    __half* hpT   = (__half*)(smraw + OFF_HPT);
    char*   h16   = smraw + OFF_H16;
    char*   edpB  = smraw + OFF_EDP;
    float*  Es_s  = (float*)(smraw + OFF_ES);
    float*  Es02_s = (float*)(smraw + OFF_ES02);
    const uint32_t sb = smem_u32(smraw);

    const int bh = blockIdx.x;
    const int head = bh & 7;
    const int b = bh >> 3;
    const int tid = threadIdx.x;
    const int warp = tid >> 5;
    const int lane = tid & 31;
    const int q = lane >> 2;
    const int c = lane & 3;

    // ======================= Phase 1: GEMM -> hpT =======================
    const int dt = warp >> 1;      // d-tile 0..3
    const int sub = warp & 1;      // m-eighth selector within pass
    const int row0 = dt * 16 + q;
    const __half* wbase = g_W16 + ((size_t)head * HD) * ID;

    for (int pass = 0; pass < 2; pass++) {
        float acc[16][4];
        #pragma unroll
        for (int f = 0; f < 16; f++)
            #pragma unroll
            for (int j = 0; j < 4; j++) acc[f][j] = 0.f;

        const __half* hsrc = g_h16 + (size_t)(b * NA + pass * 256 + tid) * ID;
        const uint32_t myslot = sb + OFF_H16 + tid * 32;

        // tables ride in pass-0 group 0
        if (pass == 0 && tid < 128) {
            cp_async16(sb + OFF_EDP + tid * 16, g_Edp + bh * 2048 + tid * 16);
            cp_async16(sb + OFF_ES + tid * 16, g_Es + bh * NA + tid * 4);
            cp_async16(sb + OFF_ES02 + tid * 16, g_Es02 + bh * NA + tid * 4);
        }
        cp_async16(myslot, hsrc);                      // chunk 0 -> buf 0
        cp_async16(myslot + 16, hsrc + 8);
        CP_COMMIT();
        cp_async16(myslot + 8192, hsrc + 16);          // chunk 1 -> buf 1
        cp_async16(myslot + 8192 + 16, hsrc + 24);
        CP_COMMIT();

        uint2 wf0 = *(const uint2*)(wbase + row0 * 128 + c * 4);
        uint2 wf1 = *(const uint2*)(wbase + (row0 + 8) * 128 + c * 4);

        #pragma unroll
        for (int kc = 0; kc < 8; kc++) {
            if (kc < 7) { CP_WAIT1(); } else { CP_WAIT0(); }
            __syncthreads();
            if (kc < 6) {
                const uint32_t d2 = sb + OFF_H16 + ((kc + 2) % 3) * 8192 + tid * 32;
                cp_async16(d2, hsrc + (kc + 2) * 16);
                cp_async16(d2 + 16, hsrc + (kc + 2) * 16 + 8);
                CP_COMMIT();
            }
            uint2 nf0, nf1;
            if (kc < 7) {
                nf0 = *(const uint2*)(wbase + row0 * 128 + (kc + 1) * 16 + c * 4);
                nf1 = *(const uint2*)(wbase + (row0 + 8) * 128 + (kc + 1) * 16 + c * 4);
            }
            const char* hb = h16 + (kc % 3) * 8192;
            #pragma unroll
            for (int nf = 0; nf < 16; nf++) {
                const int ml = sub * 128 + nf * 8 + q;
                uint2 bhv = *(const uint2*)(hb + ml * 32 + c * 8);
                mma_f16(acc[nf], wf0.x, wf1.x, wf0.y, wf1.y, bhv.x, bhv.y);
            }
            wf0 = nf0; wf1 = nf1;
        }

        // store pass acc -> hpT (fp16, permuted m), mq_eff = pass*2+sub
        {
            const int mqe = pass * 2 + sub;
            char* r0p = (char*)hpT + (row0 * HPTH_S + mqe * 128 + c * 4) * 2;
            char* r1p = r0p + 8 * HPTH_S * 2;
            #pragma unroll
            for (int nf = 0; nf < 16; nf++) {
                const int off = ((nf >> 1) * 16 + (nf & 1) * 2) * 2;
                __half2 p0 = __floats2half2_rn(acc[nf][0], acc[nf][1]);
                __half2 p1 = __floats2half2_rn(acc[nf][2], acc[nf][3]);
                *(uint32_t*)(r0p + off) = h2u(p0);
                *(uint32_t*)(r1p + off) = h2u(p1);
            }
        }
        __syncthreads();   // buffers free + hpT pass visible
    }

    // =================== Phase 2: attention (2 row passes) ===============
    const uint32_t ONE2 = 0x3C003C00u;
    const char* bbase = (const char*)hpT + (q * HPTH_S + c * 4) * 2;
    const char* eb = edpB + c * 16;

    #pragma unroll 1
    for (int p = 0; p < 2; p++) {
        const int r0 = p * 256 + warp * 32 + q;
        const uint32_t EsA0h = h2u(__float2half2_rn(Es_s[r0]));
        const uint32_t EsA1h = h2u(__float2half2_rn(Es_s[r0 + 8]));
        const uint32_t EsB0h = h2u(__float2half2_rn(Es_s[r0 + 16]));
        const uint32_t EsB1h = h2u(__float2half2_rn(Es_s[r0 + 24]));
        const uint32_t EtA0h = h2u(__float2half2_rn(Es02_s[r0]));
        const uint32_t EtA1h = h2u(__float2half2_rn(Es02_s[r0 + 8]));
        const uint32_t EtB0h = h2u(__float2half2_rn(Es02_s[r0 + 16]));
        const uint32_t EtB1h = h2u(__float2half2_rn(Es02_s[r0 + 24]));

        float dA[8][4], dB[8][4], dSA[4], dSB[4];
        #pragma unroll
        for (int t = 0; t < 8; t++)
            #pragma unroll
            for (int j = 0; j < 4; j++) { dA[t][j] = 0.f; dB[t][j] = 0.f; }
        #pragma unroll
        for (int j = 0; j < 4; j++) { dSA[j] = 0.f; dSB[j] = 0.f; }

        uint4 e4 = *(const uint4*)(eb);
        #pragma unroll 2
        for (int K = 0; K < 32; K++) {
            const uint4 e4n = *(const uint4*)(eb + (K + 1) * 64);  // K=31 -> pad

            const uint32_t a0 = hmax2u(hmul2u(EsA0h, e4.x), hmul2u(EtA0h, e4.y));
            const uint32_t a1 = hmax2u(hmul2u(EsA1h, e4.x), hmul2u(EtA1h, e4.y));
            const uint32_t a2 = hmax2u(hmul2u(EsA0h, e4.z), hmul2u(EtA0h, e4.w));
            const uint32_t a3 = hmax2u(hmul2u(EsA1h, e4.z), hmul2u(EtA1h, e4.w));
            const uint32_t a4 = hmax2u(hmul2u(EsB0h, e4.x), hmul2u(EtB0h, e4.y));
            const uint32_t a5 = hmax2u(hmul2u(EsB1h, e4.x), hmul2u(EtB1h, e4.y));
            const uint32_t a6 = hmax2u(hmul2u(EsB0h, e4.z), hmul2u(EtB0h, e4.w));
            const uint32_t a7 = hmax2u(hmul2u(EsB1h, e4.z), hmul2u(EtB1h, e4.w));

            mma_f16(dSA, a0, a1, a2, a3, ONE2, ONE2);
            mma_f16(dSB, a4, a5, a6, a7, ONE2, ONE2);

            const char* bk = bbase + K * 32;
            #pragma unroll
            for (int dtf = 0; dtf < 8; dtf++) {
                const uint2 b2 = *(const uint2*)(bk + dtf * (8 * HPTH_S * 2));
                mma_f16(dA[dtf], a0, a1, a2, a3, b2.x, b2.y);
                mma_f16(dB[dtf], a4, a5, a6, a7, b2.x, b2.y);
            }
            e4 = e4n;
        }

        const float ivA0 = 1.f / dSA[0], ivA1 = 1.f / dSA[2];
        const float ivB0 = 1.f / dSB[0], ivB1 = 1.f / dSB[2];

        const size_t orow = ((size_t)bh * NA + r0) * HD;
        float* o0 = out + orow;
        float* o1 = o0 + 8 * HD;
        float* o2 = o0 + 16 * HD;
        float* o3 = o0 + 24 * HD;
        #pragma unroll
        for (int dtf = 0; dtf < 8; dtf++) {
            const int dc = dtf * 8 + 2 * c;
            float2 v;
            v.x = elu1(dA[dtf][0] * ivA0); v.y = elu1(dA[dtf][1] * ivA0);
            *(float2*)&o0[dc] = v;
            v.x = elu1(dA[dtf][2] * ivA1); v.y = elu1(dA[dtf][3] * ivA1);
            *(float2*)&o1[dc] = v;
            v.x = elu1(dB[dtf][0] * ivB0); v.y = elu1(dB[dtf][1] * ivB0);
            *(float2*)&o2[dc] = v;
            v.x = elu1(dB[dtf][2] * ivB1); v.y = elu1(dB[dtf][3] * ivB1);
            *(float2*)&o3[dc] = v;
        }
    }
}

// ---------------------------------------------------------------------------
extern "C" void kernel_launch(void* const* d_in, const int* in_sizes, int n_in,
                              void* d_out, int out_size)
{
    const float* h     = (const float*)d_in[0];
    const float* W     = (const float*)d_in[1];
    const float* att_a = (const float*)d_in[2];
    float* out = (float*)d_out;

    cudaFuncSetAttribute(gat_main,
        cudaFuncAttributeMaxDynamicSharedMemorySize, SMEM_M_BYTES);

    prep_all<<<256, 512>>>(h, W, att_a);
    gat_main<<<256, 256, SMEM_M_BYTES>>>(out);
}

// round 17
// speedup vs baseline: 1.4842x; 1.4842x over previous
#include <cuda_runtime.h>
#include <cuda_fp16.h>
#include <math.h>
#include <stdint.h>

#define NEG_SLOPE 0.2f
#define LOG2E 1.4426950408889634f

// Problem constants
#define BS 32
#define NA 512          // n_agents
#define ID 128          // input_dim
#define NH 8            // n_heads
#define HD 64           // hidden_dim

// ---------------------------------------------------------------------------
// Global scratch (conversion outputs)
// ---------------------------------------------------------------------------
__device__ __half g_h16[BS * NA * ID];      // [b][m][pk]        4 MB
__device__ __half g_W16[NH * HD * ID];      // [head][d][pk]     128 KB

// ---------------------------------------------------------------------------
// helpers
// ---------------------------------------------------------------------------
__device__ __forceinline__ float ex2(float x) {
    float r;
    asm("ex2.approx.f32 %0, %1;" : "=f"(r) : "f"(x));
    return r;
}
__device__ __forceinline__ uint32_t smem_u32(const void* p) {
    uint32_t a;
    asm("{ .reg .u64 t; cvta.to.shared.u64 t, %1; cvt.u32.u64 %0, t; }"
        : "=r"(a) : "l"(p));
    return a;
}
__device__ __forceinline__ void cp_async16(uint32_t dst, const void* src) {
    asm volatile("cp.async.cg.shared.global [%0], [%1], 16;"
                 :: "r"(dst), "l"(src) : "memory");
}
#define CP_COMMIT() asm volatile("cp.async.commit_group;" ::: "memory")
#define CP_WAIT0()  asm volatile("cp.async.wait_group 0;" ::: "memory")
#define CP_WAIT1()  asm volatile("cp.async.wait_group 1;" ::: "memory")

__device__ __forceinline__ void mma_f16(float d[4], uint32_t a0, uint32_t a1,
                                        uint32_t a2, uint32_t a3,
                                        uint32_t b0, uint32_t b1) {
    asm volatile(
        "mma.sync.aligned.m16n8k16.row.col.f32.f16.f16.f32 "
        "{%0,%1,%2,%3}, {%4,%5,%6,%7}, {%8,%9}, {%0,%1,%2,%3};"
        : "+f"(d[0]), "+f"(d[1]), "+f"(d[2]), "+f"(d[3])
        : "r"(a0), "r"(a1), "r"(a2), "r"(a3), "r"(b0), "r"(b1));
}
__device__ __forceinline__ float elu1(float x) {
    return x > 0.f ? x : expm1f(x);
}
__device__ __forceinline__ uint32_t h2u(__half2 v) {
    return *reinterpret_cast<uint32_t*>(&v);
}
__device__ __forceinline__ uint32_t hmul2u(uint32_t x, uint32_t y) {
    __half2 r = __hmul2(*reinterpret_cast<__half2*>(&x),
                        *reinterpret_cast<__half2*>(&y));
    return h2u(r);
}
__device__ __forceinline__ uint32_t hmax2u(uint32_t x, uint32_t y) {
    __half2 r = __hmax2(*reinterpret_cast<__half2*>(&x),
                        *reinterpret_cast<__half2*>(&y));
    return h2u(r);
}

// ---------------------------------------------------------------------------
// Prep: pure fp32 -> fp16 conversion of h and W (k-permuted), grid 256 x 256.
//   phys cc*4+{0,1,2,3} = logical {2cc, 2cc+1, 2cc+8, 2cc+9}
// ---------------------------------------------------------------------------
__global__ void conv_hw(const float* __restrict__ h, const float* __restrict__ W) {
    const int idx = blockIdx.x * 256 + threadIdx.x;   // 65536 tasks

    // h: one quarter-row (32 elems) per thread
    {
        const int row = idx >> 2, qt = idx & 3;
        const float* src = h + (size_t)row * ID + qt * 32;
        __half* dst = g_h16 + (size_t)row * ID + qt * 32;
        #pragma unroll
        for (int g = 0; g < 2; g++) {
            float v[16];
            #pragma unroll
            for (int i = 0; i < 4; i++)
                *(float4*)&v[i * 4] = *(const float4*)&src[g * 16 + i * 4];
            #pragma unroll
            for (int cc = 0; cc < 4; cc++) {
                __half2 lo = __floats2half2_rn(v[2 * cc], v[2 * cc + 1]);
                __half2 hi = __floats2half2_rn(v[2 * cc + 8], v[2 * cc + 9]);
                *(uint2*)(dst + g * 16 + cc * 4) = make_uint2(h2u(lo), h2u(hi));
            }
        }
    }

    // W: one element per thread (coalesced read)
    {
        const int k = idx >> 9, col = idx & 511;
        const int head = col >> 6, d = col & 63;
        const int L = k & 15;
        const int pk = (k & ~15) + ((L >> 1) & 3) * 4 + ((L >> 3) << 1) + (L & 1);
        g_W16[((head * 64 + d) << 7) + pk] = __float2half_rn(W[idx]);
    }
}

// ---------------------------------------------------------------------------
// Main kernel: 256 threads, 2 CTAs/SM, grid 256 (one per (b,h)).
// Phase 1: hpT fp16 GEMM (cp.async 3-buffer ring for h16, LDG W frags).
// Phase 1.5: e-scores from hpT in SMEM (2 columns/thread) -> factor tables.
// Phase 2: attention (2 row passes of 32 rows/warp, full m-scan).
// ---------------------------------------------------------------------------
#define HPTH_S 528
#define OFF_HPT   0                                   // half [64][528] 67584
#define OFF_H16   67584                               // 3 x [256][16] half
#define OFF_EDP   (OFF_H16 + 3 * 8192)                // 92160: 2048 + 64 pad
#define OFF_ES    (OFF_EDP + 2048 + 64)               // 94272
#define OFF_ES02  (OFF_ES + 2048)                     // 96320
#define OFF_RED   (OFF_ES02 + 2048)                   // 98368
#define SMEM_M_BYTES (OFF_RED + 64)                   // 98432

__global__ void __launch_bounds__(256, 2) gat_main(
    const float* __restrict__ att_a, float* __restrict__ out)
{
    extern __shared__ char smraw[];
    __half* hpT    = (__half*)(smraw + OFF_HPT);
    char*   h16    = smraw + OFF_H16;
    char*   edpB   = smraw + OFF_EDP;
    float*  Es_s   = (float*)(smraw + OFF_ES);
    float*  Es02_s = (float*)(smraw + OFF_ES02);
    float*  red_s  = (float*)(smraw + OFF_RED);
    const uint32_t sb = smem_u32(smraw);

    const int bh = blockIdx.x;
    const int head = bh & 7;
    const int b = bh >> 3;
    const int tid = threadIdx.x;
    const int warp = tid >> 5;
    const int lane = tid & 31;
    const int q = lane >> 2;
    const int c = lane & 3;

    // a_s lives in the (not yet used) Es slot during phase 1/1.5 prologue
    float* a_s = Es_s;   // reused before Es is written? NO - Es written in 1.5.
    // Safer: stash att_a in registers per thread group via shared red area is
    // too small; instead load a into the tail of edpB region (2048+64 >= 512B
    // needed for 128 floats? 128*4 = 512B; edpB is free until phase 1.5).
    float* att_s = (float*)edpB;   // 128 floats, overwritten later by granules
    if (tid < 128) att_s[tid] = att_a[head * 128 + tid];

    // ======================= Phase 1: GEMM -> hpT =======================
    const int dt = warp >> 1;      // d-tile 0..3
    const int sub = warp & 1;      // m-eighth selector within pass
    const int row0 = dt * 16 + q;
    const __half* wbase = g_W16 + ((size_t)head * HD) * ID;

    for (int pass = 0; pass < 2; pass++) {
        float acc[16][4];
        #pragma unroll
        for (int f = 0; f < 16; f++)
            #pragma unroll
            for (int j = 0; j < 4; j++) acc[f][j] = 0.f;

        const __half* hsrc = g_h16 + (size_t)(b * NA + pass * 256 + tid) * ID;
        const uint32_t myslot = sb + OFF_H16 + tid * 32;

        cp_async16(myslot, hsrc);                      // chunk 0 -> buf 0
        cp_async16(myslot + 16, hsrc + 8);
        CP_COMMIT();
        cp_async16(myslot + 8192, hsrc + 16);          // chunk 1 -> buf 1
        cp_async16(myslot + 8192 + 16, hsrc + 24);
        CP_COMMIT();

        uint2 wf0 = *(const uint2*)(wbase + row0 * 128 + c * 4);
        uint2 wf1 = *(const uint2*)(wbase + (row0 + 8) * 128 + c * 4);

        #pragma unroll
        for (int kc = 0; kc < 8; kc++) {
            if (kc < 7) { CP_WAIT1(); } else { CP_WAIT0(); }
            __syncthreads();
            if (kc < 6) {
                const uint32_t d2 = sb + OFF_H16 + ((kc + 2) % 3) * 8192 + tid * 32;
                cp_async16(d2, hsrc + (kc + 2) * 16);
                cp_async16(d2 + 16, hsrc + (kc + 2) * 16 + 8);
                CP_COMMIT();
            }
            uint2 nf0, nf1;
            if (kc < 7) {
                nf0 = *(const uint2*)(wbase + row0 * 128 + (kc + 1) * 16 + c * 4);
                nf1 = *(const uint2*)(wbase + (row0 + 8) * 128 + (kc + 1) * 16 + c * 4);
            }
            const char* hb = h16 + (kc % 3) * 8192;
            #pragma unroll
            for (int nf = 0; nf < 16; nf++) {
                const int ml = sub * 128 + nf * 8 + q;
                uint2 bhv = *(const uint2*)(hb + ml * 32 + c * 8);
                mma_f16(acc[nf], wf0.x, wf1.x, wf0.y, wf1.y, bhv.x, bhv.y);
            }
            wf0 = nf0; wf1 = nf1;
        }

        // store pass acc -> hpT (fp16, permuted m), mq_eff = pass*2+sub
        {
            const int mqe = pass * 2 + sub;
            char* r0p = (char*)hpT + (row0 * HPTH_S + mqe * 128 + c * 4) * 2;
            char* r1p = r0p + 8 * HPTH_S * 2;
            #pragma unroll
            for (int nf = 0; nf < 16; nf++) {
                const int off = ((nf >> 1) * 16 + (nf & 1) * 2) * 2;
                __half2 p0 = __floats2half2_rn(acc[nf][0], acc[nf][1]);
                __half2 p1 = __floats2half2_rn(acc[nf][2], acc[nf][3]);
                *(uint32_t*)(r0p + off) = h2u(p0);
                *(uint32_t*)(r1p + off) = h2u(p1);
            }
        }
        __syncthreads();
    }

    // =================== Phase 1.5: e-scores from hpT ===================
    // Each thread handles physical columns tid and tid+256.
    {
        float a_reg[4];   // nothing needed; use att_s directly (smem)
        (void)a_reg;
        float es2[2], ed2[2];
        #pragma unroll
        for (int hf = 0; hf < 2; hf++) {
            const int pc = tid + hf * 256;
            float es = 0.f, ed = 0.f;
            #pragma unroll
            for (int d = 0; d < 64; d++) {
                float hp = __half2float(hpT[d * HPTH_S + pc]);
                es += hp * att_s[d];
                ed += hp * att_s[64 + d];
            }
            es2[hf] = es; ed2[hf] = ed;
        }

        // global edmax
        float em = fmaxf(ed2[0], ed2[1]);
        #pragma unroll
        for (int o = 16; o; o >>= 1)
            em = fmaxf(em, __shfl_xor_sync(0xFFFFFFFFu, em, o));
        if (lane == 0) red_s[warp] = em;
        __syncthreads();   // also: all att_s reads done before edpB overwrite
        em = red_s[0];
        #pragma unroll
        for (int i = 1; i < 8; i++) em = fmaxf(em, red_s[i]);

        #pragma unroll
        for (int hf = 0; hf < 2; hf++) {
            const int pc = tid + hf * 256;
            const int w = pc & 15;
            const int a = (pc & ~15) | (((w >> 1) & 1) << 3) | ((w >> 2) << 1) | (w & 1);

            const float edl = (ed2[hf] - em) * LOG2E;
            const __half Edh   = __float2half_rn(ex2(edl));
            const __half Ed02h = __float2half_rn(ex2(NEG_SLOPE * edl));
            const int K = a >> 4, s = (a >> 3) & 1, cc = (a >> 1) & 3, j = a & 1;
            char* g = edpB + (K * 8 + cc * 2 + s) * 8;
            *(__half*)(g + j * 2)     = Edh;
            *(__half*)(g + 4 + j * 2) = Ed02h;

            const float e0l = (es2[hf] + em) * LOG2E;
            const float rm = fmaxf(e0l, NEG_SLOPE * e0l);
            Es_s[a]   = ex2(es2[hf] * LOG2E + em * LOG2E - rm);
            Es02_s[a] = ex2(NEG_SLOPE * e0l - rm);
        }
    }
    __syncthreads();

    // =================== Phase 2: attention (2 row passes) ===============
    const uint32_t ONE2 = 0x3C003C00u;
    const char* bbase = (const char*)hpT + (q * HPTH_S + c * 4) * 2;
    const char* eb = edpB + c * 16;

    #pragma unroll 1
    for (int p = 0; p < 2; p++) {
        const int r0 = p * 256 + warp * 32 + q;
        const uint32_t EsA0h = h2u(__float2half2_rn(Es_s[r0]));
        const uint32_t EsA1h = h2u(__float2half2_rn(Es_s[r0 + 8]));
        const uint32_t EsB0h = h2u(__float2half2_rn(Es_s[r0 + 16]));
        const uint32_t EsB1h = h2u(__float2half2_rn(Es_s[r0 + 24]));
        const uint32_t EtA0h = h2u(__float2half2_rn(Es02_s[r0]));
        const uint32_t EtA1h = h2u(__float2half2_rn(Es02_s[r0 + 8]));
        const uint32_t EtB0h = h2u(__float2half2_rn(Es02_s[r0 + 16]));
        const uint32_t EtB1h = h2u(__float2half2_rn(Es02_s[r0 + 24]));

        float dA[8][4], dB[8][4], dSA[4], dSB[4];
        #pragma unroll
        for (int t = 0; t < 8; t++)
            #pragma unroll
            for (int j = 0; j < 4; j++) { dA[t][j] = 0.f; dB[t][j] = 0.f; }
        #pragma unroll
        for (int j = 0; j < 4; j++) { dSA[j] = 0.f; dSB[j] = 0.f; }

        uint4 e4 = *(const uint4*)(eb);
        #pragma unroll 2
        for (int K = 0; K < 32; K++) {
            const uint4 e4n = *(const uint4*)(eb + (K + 1) * 64);  // K=31 -> pad

            const uint32_t a0 = hmax2u(hmul2u(EsA0h, e4.x), hmul2u(EtA0h, e4.y));
            const uint32_t a1 = hmax2u(hmul2u(EsA1h, e4.x), hmul2u(EtA1h, e4.y));
            const uint32_t a2 = hmax2u(hmul2u(EsA0h, e4.z), hmul2u(EtA0h, e4.w));
            const uint32_t a3 = hmax2u(hmul2u(EsA1h, e4.z), hmul2u(EtA1h, e4.w));
            const uint32_t a4 = hmax2u(hmul2u(EsB0h, e4.x), hmul2u(EtB0h, e4.y));
            const uint32_t a5 = hmax2u(hmul2u(EsB1h, e4.x), hmul2u(EtB1h, e4.y));
            const uint32_t a6 = hmax2u(hmul2u(EsB0h, e4.z), hmul2u(EtB0h, e4.w));
            const uint32_t a7 = hmax2u(hmul2u(EsB1h, e4.z), hmul2u(EtB1h, e4.w));

            mma_f16(dSA, a0, a1, a2, a3, ONE2, ONE2);
            mma_f16(dSB, a4, a5, a6, a7, ONE2, ONE2);

            const char* bk = bbase + K * 32;
            #pragma unroll
            for (int dtf = 0; dtf < 8; dtf++) {
                const uint2 b2 = *(const uint2*)(bk + dtf * (8 * HPTH_S * 2));
                mma_f16(dA[dtf], a0, a1, a2, a3, b2.x, b2.y);
                mma_f16(dB[dtf], a4, a5, a6, a7, b2.x, b2.y);
            }
            e4 = e4n;
        }

        const float ivA0 = 1.f / dSA[0], ivA1 = 1.f / dSA[2];
        const float ivB0 = 1.f / dSB[0], ivB1 = 1.f / dSB[2];

        const size_t orow = ((size_t)bh * NA + r0) * HD;
        float* o0 = out + orow;
        float* o1 = o0 + 8 * HD;
        float* o2 = o0 + 16 * HD;
        float* o3 = o0 + 24 * HD;
        #pragma unroll
        for (int dtf = 0; dtf < 8; dtf++) {
            const int dc = dtf * 8 + 2 * c;
            float2 v;
            v.x = elu1(dA[dtf][0] * ivA0); v.y = elu1(dA[dtf][1] * ivA0);
            *(float2*)&o0[dc] = v;
            v.x = elu1(dA[dtf][2] * ivA1); v.y = elu1(dA[dtf][3] * ivA1);
            *(float2*)&o1[dc] = v;
            v.x = elu1(dB[dtf][0] * ivB0); v.y = elu1(dB[dtf][1] * ivB0);
            *(float2*)&o2[dc] = v;
            v.x = elu1(dB[dtf][2] * ivB1); v.y = elu1(dB[dtf][3] * ivB1);
            *(float2*)&o3[dc] = v;
        }
    }
}

// ---------------------------------------------------------------------------
extern "C" void kernel_launch(void* const* d_in, const int* in_sizes, int n_in,
                              void* d_out, int out_size)
{
    const float* h     = (const float*)d_in[0];
    const float* W     = (const float*)d_in[1];
    const float* att_a = (const float*)d_in[2];
    float* out = (float*)d_out;

    cudaFuncSetAttribute(gat_main,
        cudaFuncAttributeMaxDynamicSharedMemorySize, SMEM_M_BYTES);

    conv_hw<<<256, 256>>>(h, W);
    gat_main<<<256, 256, SMEM_M_BYTES>>>(att_a, out);
}